// round 10
// baseline (speedup 1.0000x reference)
#include <cuda_runtime.h>
#include <cstdint>

// ---------------------------------------------------------------------------
// DifferentiableBiquadChain: 16 cascaded SVF biquads, per-frame coefficients.
//
// Block = (batch b, frame f), 128 threads. Each WARP owns a 512-sample
// segment and runs the whole cascade autonomously — no per-filter block
// barriers. Per filter: [warp0: prefetch predecessor-frame state] ->
// zero-state sim (16 samples/thread) -> warp affine scan (constant-A,
// powers by repeated squaring) -> spin on predecessor warp's published
// state (smem volatile 64-bit slot; warp0 uses global g_state) -> lane31
// publishes own out-state (smem for w<3, global for w==3) -> thread-in
// state -> exact re-sim with reference arithmetic. Audio in registers.
// ---------------------------------------------------------------------------

#define NB      16
#define FRAME   2048
#define NFR     24
#define BATCH   32
#define TPB     128
#define SPT     16
#define SVAL    0xFFFFFFFFFFFFFFFFull

typedef unsigned long long ull;

__device__ ull g_state[BATCH * NFR * NB];

__global__ void init_state_kernel() {
    int i = blockIdx.x * blockDim.x + threadIdx.x;
    if (i < BATCH * NFR * NB) g_state[i] = SVAL;
}

struct M2 { float a, b, c, d; }; // [[a,b],[c,d]]

__device__ __forceinline__ M2 msq(M2 m) {
    M2 r;
    float apd = m.a + m.d;
    float bc  = m.b * m.c;
    r.a = fmaf(m.a, m.a, bc);
    r.b = m.b * apd;
    r.c = m.c * apd;
    r.d = fmaf(m.d, m.d, bc);
    return r;
}

__device__ __forceinline__ M2 mmul(M2 p, M2 q) {
    M2 r;
    r.a = fmaf(p.a, q.a, p.b * q.c);
    r.b = fmaf(p.a, q.b, p.b * q.d);
    r.c = fmaf(p.c, q.a, p.d * q.c);
    r.d = fmaf(p.c, q.b, p.d * q.d);
    return r;
}

__device__ __forceinline__ ull ld_relaxed_u64(const ull* p) {
    ull v;
    asm volatile("ld.relaxed.gpu.global.u64 %0, [%1];" : "=l"(v) : "l"(p) : "memory");
    return v;
}
__device__ __forceinline__ void st_relaxed_u64(ull* p, ull v) {
    asm volatile("st.relaxed.gpu.global.u64 [%0], %1;" : : "l"(p), "l"(v) : "memory");
}

__global__ __launch_bounds__(TPB, 6)
void eq_kernel(const float* __restrict__ audio,
               const float* __restrict__ params,
               float* __restrict__ out)
{
    const int blk  = blockIdx.x;
    const int f    = blk >> 5;   // frame (f-major: predecessors have lower blockIdx)
    const int b    = blk & 31;   // batch
    const int t    = threadIdx.x;
    const int lane = t & 31;
    const int w    = t >> 5;

    __shared__ float cf[NB][6];        // a1 a2 a3 m0 m1 m2
    __shared__ float sh_gain[2];       // in_g, out_g
    __shared__ ull   sh_pub[3][NB];    // warp w (<3) publishes filter-i state here

    // ---------------- setup (single barrier) ----------------
    if (t < NB) {
        const float* pb = params + (size_t)(b * 50) * NFR + f;
        float fn = pb[(t * 3 + 0) * NFR];
        float gn = pb[(t * 3 + 1) * NFR];
        float qn = pb[(t * 3 + 2) * NFR];

        float Q = expf(fmaf(qn, 3.4657359f, -0.6931472f));
        Q = fminf(fmaxf(Q, 0.1f), 100.0f);

        float gain = fmaf(gn, 48.0f, -24.0f);
        float A  = exp10f(gain * 0.025f);   // 10^(gain/40)
        float sA = sqrtf(A);

        float lnlo, lnhi;
        if      (t == 0)            { lnlo = 2.9957323f; lnhi = 6.2146081f; } // HPF 20..500
        else if (t == 15)           { lnlo = 8.5171932f; lnhi = 9.9034876f; } // LPF 5k..20k
        else if (t == 1 || t == 14) { lnlo = 3.9120230f; lnhi = 9.6803184f; } // shelf 50..16k
        else                        { lnlo = 4.6051702f; lnhi = 9.6158055f; } // peak 100..15k
        float fc = expf(fmaf(fn, (lnhi - lnlo), lnlo));
        float g  = tanf(fc * 3.27249235e-5f);           // tan(pi*fc/96000)
        g = fminf(fmaxf(g, 1e-6f), 100.0f);

        float a1, a2, a3, m0, m1, m2;
        if (t == 0) {            // highpass
            float k = 1.0f / Q;
            a1 = 1.0f / (1.0f + g * (g + k)); a2 = g * a1; a3 = g * a2;
            m0 = 1.0f; m1 = -k; m2 = -1.0f;
        } else if (t == 15) {    // lowpass
            float k = 1.0f / Q;
            a1 = 1.0f / (1.0f + g * (g + k)); a2 = g * a1; a3 = g * a2;
            m0 = 0.0f; m1 = 0.0f; m2 = 1.0f;
        } else if (t == 1) {     // lowshelf
            float k = 1.0f / Q;
            float gs = (gain >= 0.0f) ? (g / sA) : (g * sA);
            a1 = 1.0f / (1.0f + gs * (gs + k)); a2 = gs * a1; a3 = gs * a2;
            m0 = 1.0f; m1 = k * (A - 1.0f); m2 = A * A - 1.0f;
        } else if (t == 14) {    // highshelf
            float k = 1.0f / Q;
            float gs = (gain >= 0.0f) ? (g * sA) : (g / sA);
            a1 = 1.0f / (1.0f + gs * (gs + k)); a2 = gs * a1; a3 = gs * a2;
            m0 = A * A; m1 = k * (1.0f - A) * A; m2 = 1.0f - A * A;
        } else {                 // peak
            float k = (gain >= 0.0f) ? (1.0f / (Q * A)) : (A / Q);
            a1 = 1.0f / (1.0f + g * (g + k)); a2 = g * a1; a3 = g * a2;
            m0 = 1.0f; m1 = k * (A * A - 1.0f); m2 = 0.0f;
        }
        cf[t][0] = a1; cf[t][1] = a2; cf[t][2] = a3;
        cf[t][3] = m0; cf[t][4] = m1; cf[t][5] = m2;
    } else if (t == 16 || t == 17) {
        float n  = params[(size_t)(b * 50 + 48 + (t - 16)) * NFR + f];
        float db = fmaf(n, 60.0f, -60.0f);
        sh_gain[t - 16] = exp10f(db * 0.05f);  // 10^(db/20)
    } else if (t >= 64 && t < 64 + 3 * NB) {
        int idx = t - 64;
        sh_pub[idx >> 4][idx & 15] = SVAL;
    }
    __syncthreads();   // the only block barrier

    // ---------------- load audio (x stays in registers) ----------------
    const float ing  = sh_gain[0];
    const float outg = sh_gain[1];
    float x[SPT];
    {
        const float4* ap = (const float4*)(audio + (size_t)b * 49152 + f * FRAME + t * SPT);
        #pragma unroll
        for (int j = 0; j < 4; j++) {
            float4 v = ap[j];
            x[4 * j + 0] = v.x * ing;
            x[4 * j + 1] = v.y * ing;
            x[4 * j + 2] = v.z * ing;
            x[4 * j + 3] = v.w * ing;
        }
    }

    const ull* src_base = (f > 0) ? &g_state[((size_t)b * NFR + (f - 1)) * NB] : nullptr;
    ull* dst_base = (f < NFR - 1) ? &g_state[((size_t)b * NFR + f) * NB] : nullptr;
    volatile ull* my_spin = (w > 0) ? &sh_pub[w - 1][0] : nullptr;   // pred warp's slots
    volatile ull* my_pub  = (w < 3) ? &sh_pub[w][0] : nullptr;       // own publish slots

    // ---------------- filter cascade (warp-autonomous) ----------------
    for (int i = 0; i < NB; i++) {
        const float a1 = cf[i][0], a2 = cf[i][1], a3 = cf[i][2];
        const float m0 = cf[i][3], m1 = cf[i][4], m2 = cf[i][5];

        // warp 0: prefetch predecessor frame state (broadcast load; latency
        // hidden under zero-sim + scan)
        ull v = 0ull;
        if (w == 0 && f > 0) v = ld_relaxed_u64(src_base + i);

        // zero-state sim over this thread's 16 samples -> segment offset (c1,c2)
        float c1 = 0.0f, c2 = 0.0f;
        #pragma unroll
        for (int j = 0; j < SPT; j++) {
            float v3 = x[j] - c2;
            float v1 = fmaf(a1, c1, a2 * v3);
            float v2 = fmaf(a2, v1, fmaf(a3, v3, c2));
            c1 = fmaf(2.0f, v1, -c1);
            c2 = fmaf(2.0f, v2, -c2);
        }

        // state transition A, then A^16
        M2 M;
        M.a = fmaf(2.0f, a1, -1.0f);
        M.b = -2.0f * a2;
        M.c = 2.0f * a1 * a2;
        M.d = 1.0f - 2.0f * fmaf(a2, a2, a3);
        M = msq(msq(msq(msq(M))));  // A^16

        // warp affine scan; simultaneously build L = A^(16*lane)
        M2 L; L.a = 1.0f; L.b = 0.0f; L.c = 0.0f; L.d = 1.0f;
        #pragma unroll
        for (int k = 0; k < 5; k++) {
            float o1 = __shfl_up_sync(0xFFFFFFFFu, c1, 1 << k);
            float o2 = __shfl_up_sync(0xFFFFFFFFu, c2, 1 << k);
            if (lane >= (1 << k)) {
                c1 = fmaf(M.a, o1, fmaf(M.b, o2, c1));
                c2 = fmaf(M.c, o1, fmaf(M.d, o2, c2));
            }
            if (lane & (1 << k)) L = mmul(M, L);
            M = msq(M);             // after loop: M = A^512
        }

        // within-warp exclusive offset
        float e1 = __shfl_up_sync(0xFFFFFFFFu, c1, 1);
        float e2 = __shfl_up_sync(0xFFFFFFFFu, c2, 1);
        if (lane == 0) { e1 = 0.0f; e2 = 0.0f; }

        // obtain warp-in state from predecessor (smem for w>0, global for w=0)
        if (w == 0) {
            if (f > 0 && v == SVAL) {
                do { __nanosleep(32); v = ld_relaxed_u64(src_base + i); } while (v == SVAL);
            }
        } else {
            v = my_spin[i];
            while (v == SVAL) { __nanosleep(20); v = my_spin[i]; }
        }
        const float si1 = __uint_as_float((unsigned)(v & 0xFFFFFFFFu));
        const float si2 = __uint_as_float((unsigned)(v >> 32));

        // lane 31: publish this warp's out-state = A^512 * s_in + T_own
        // (c1,c2 at lane 31 is the inclusive warp total)
        if (lane == 31) {
            float S1 = fmaf(M.a, si1, fmaf(M.b, si2, c1));
            float S2 = fmaf(M.c, si1, fmaf(M.d, si2, c2));
            ull pv = ((ull)__float_as_uint(S2) << 32) | (ull)__float_as_uint(S1);
            if (w < 3)                       my_pub[i] = pv;
            else if (dst_base != nullptr)    st_relaxed_u64(dst_base + i, pv);
        }

        // thread-in state = L * s_in + e
        float s1 = fmaf(L.a, si1, fmaf(L.b, si2, e1));
        float s2 = fmaf(L.c, si1, fmaf(L.d, si2, e2));

        // exact re-simulation producing outputs (reference arithmetic)
        #pragma unroll
        for (int j = 0; j < SPT; j++) {
            float xn = x[j];
            float v3 = xn - s2;
            float v1 = fmaf(a1, s1, a2 * v3);
            float v2 = fmaf(a2, v1, fmaf(a3, v3, s2));
            x[j] = fmaf(m0, xn, fmaf(m1, v1, m2 * v2));
            s1 = fmaf(2.0f, v1, -s1);
            s2 = fmaf(2.0f, v2, -s2);
        }
    }

    // ---------------- store output ----------------
    {
        float4* op = (float4*)(out + (size_t)b * 49152 + f * FRAME + t * SPT);
        #pragma unroll
        for (int j = 0; j < 4; j++) {
            float4 v;
            v.x = x[4 * j + 0] * outg;
            v.y = x[4 * j + 1] * outg;
            v.z = x[4 * j + 2] * outg;
            v.w = x[4 * j + 3] * outg;
            op[j] = v;
        }
    }
}

extern "C" void kernel_launch(void* const* d_in, const int* in_sizes, int n_in,
                              void* d_out, int out_size) {
    const float* audio;
    const float* params;
    if (in_sizes[0] > in_sizes[1]) { audio = (const float*)d_in[0]; params = (const float*)d_in[1]; }
    else                           { audio = (const float*)d_in[1]; params = (const float*)d_in[0]; }
    float* out = (float*)d_out;

    init_state_kernel<<<(BATCH * NFR * NB + 255) / 256, 256>>>();
    eq_kernel<<<BATCH * NFR, TPB>>>(audio, params, out);
}

// round 11
// speedup vs baseline: 1.0984x; 1.0984x over previous
#include <cuda_runtime.h>
#include <cstdint>

// ---------------------------------------------------------------------------
// DifferentiableBiquadChain: 16 cascaded SVF biquads, per-frame coefficients.
//
// Block = (batch b, frame f), 128 threads x 16 samples each.
// Per filter: prefetch predecessor frame state -> zero-state sim in TWO
// independent 8-sample halves (outputs y0 emitted on the fly) -> combine
// halves (A^8) -> warp affine scan (A^16 steps) -> ONE barrier -> per-warp
// chain -> publish (thread 0) -> SUPERPOSITION correction x += u_j . s
// (u_j = (m1,m2) W A^j, corrections parallel given s) instead of a serial
// re-simulation. Audio stays in registers across all 16 stages.
// ---------------------------------------------------------------------------

#define NB      16
#define FRAME   2048
#define NFR     24
#define BATCH   32
#define TPB     128
#define SPT     16
#define NW      4
#define SVAL    0xFFFFFFFFFFFFFFFFull

typedef unsigned long long ull;

__device__ ull g_state[BATCH * NFR * NB];

__global__ void init_state_kernel() {
    int i = blockIdx.x * blockDim.x + threadIdx.x;
    if (i < BATCH * NFR * NB) g_state[i] = SVAL;
}

struct M2 { float a, b, c, d; }; // [[a,b],[c,d]]

__device__ __forceinline__ M2 msq(M2 m) {
    M2 r;
    float apd = m.a + m.d;
    float bc  = m.b * m.c;
    r.a = fmaf(m.a, m.a, bc);
    r.b = m.b * apd;
    r.c = m.c * apd;
    r.d = fmaf(m.d, m.d, bc);
    return r;
}

__device__ __forceinline__ M2 mmul(M2 p, M2 q) {
    M2 r;
    r.a = fmaf(p.a, q.a, p.b * q.c);
    r.b = fmaf(p.a, q.b, p.b * q.d);
    r.c = fmaf(p.c, q.a, p.d * q.c);
    r.d = fmaf(p.c, q.b, p.d * q.d);
    return r;
}

__device__ __forceinline__ ull ld_relaxed_u64(const ull* p) {
    ull v;
    asm volatile("ld.relaxed.gpu.global.u64 %0, [%1];" : "=l"(v) : "l"(p) : "memory");
    return v;
}
__device__ __forceinline__ void st_relaxed_u64(ull* p, ull v) {
    asm volatile("st.relaxed.gpu.global.u64 [%0], %1;" : : "l"(p), "l"(v) : "memory");
}

__global__ __launch_bounds__(TPB, 6)
void eq_kernel(const float* __restrict__ audio,
               const float* __restrict__ params,
               float* __restrict__ out)
{
    const int blk  = blockIdx.x;
    const int f    = blk >> 5;   // frame (f-major: predecessors have lower blockIdx)
    const int b    = blk & 31;   // batch
    const int t    = threadIdx.x;
    const int lane = t & 31;
    const int w    = t >> 5;

    __shared__ float cf[NB][6];       // a1 a2 a3 m0 m1 m2
    __shared__ float sh_gain[2];      // in_g, out_g
    __shared__ float shTa[2][NW];     // warp totals c1 (double-buffered)
    __shared__ float shTb[2][NW];     // warp totals c2

    // ---------------- coefficients (threads 0..17) ----------------
    if (t < NB) {
        const float* pb = params + (size_t)(b * 50) * NFR + f;
        float fn = pb[(t * 3 + 0) * NFR];
        float gn = pb[(t * 3 + 1) * NFR];
        float qn = pb[(t * 3 + 2) * NFR];

        float Q = expf(fmaf(qn, 3.4657359f, -0.6931472f));
        Q = fminf(fmaxf(Q, 0.1f), 100.0f);

        float gain = fmaf(gn, 48.0f, -24.0f);
        float A  = exp10f(gain * 0.025f);   // 10^(gain/40)
        float sA = sqrtf(A);

        float lnlo, lnhi;
        if      (t == 0)            { lnlo = 2.9957323f; lnhi = 6.2146081f; } // HPF 20..500
        else if (t == 15)           { lnlo = 8.5171932f; lnhi = 9.9034876f; } // LPF 5k..20k
        else if (t == 1 || t == 14) { lnlo = 3.9120230f; lnhi = 9.6803184f; } // shelf 50..16k
        else                        { lnlo = 4.6051702f; lnhi = 9.6158055f; } // peak 100..15k
        float fc = expf(fmaf(fn, (lnhi - lnlo), lnlo));
        float g  = tanf(fc * 3.27249235e-5f);           // tan(pi*fc/96000)
        g = fminf(fmaxf(g, 1e-6f), 100.0f);

        float a1, a2, a3, m0, m1, m2;
        if (t == 0) {            // highpass
            float k = 1.0f / Q;
            a1 = 1.0f / (1.0f + g * (g + k)); a2 = g * a1; a3 = g * a2;
            m0 = 1.0f; m1 = -k; m2 = -1.0f;
        } else if (t == 15) {    // lowpass
            float k = 1.0f / Q;
            a1 = 1.0f / (1.0f + g * (g + k)); a2 = g * a1; a3 = g * a2;
            m0 = 0.0f; m1 = 0.0f; m2 = 1.0f;
        } else if (t == 1) {     // lowshelf
            float k = 1.0f / Q;
            float gs = (gain >= 0.0f) ? (g / sA) : (g * sA);
            a1 = 1.0f / (1.0f + gs * (gs + k)); a2 = gs * a1; a3 = gs * a2;
            m0 = 1.0f; m1 = k * (A - 1.0f); m2 = A * A - 1.0f;
        } else if (t == 14) {    // highshelf
            float k = 1.0f / Q;
            float gs = (gain >= 0.0f) ? (g * sA) : (g / sA);
            a1 = 1.0f / (1.0f + gs * (gs + k)); a2 = gs * a1; a3 = gs * a2;
            m0 = A * A; m1 = k * (1.0f - A) * A; m2 = 1.0f - A * A;
        } else {                 // peak
            float k = (gain >= 0.0f) ? (1.0f / (Q * A)) : (A / Q);
            a1 = 1.0f / (1.0f + g * (g + k)); a2 = g * a1; a3 = g * a2;
            m0 = 1.0f; m1 = k * (A * A - 1.0f); m2 = 0.0f;
        }
        cf[t][0] = a1; cf[t][1] = a2; cf[t][2] = a3;
        cf[t][3] = m0; cf[t][4] = m1; cf[t][5] = m2;
    } else if (t == 16 || t == 17) {
        float n  = params[(size_t)(b * 50 + 48 + (t - 16)) * NFR + f];
        float db = fmaf(n, 60.0f, -60.0f);
        sh_gain[t - 16] = exp10f(db * 0.05f);  // 10^(db/20)
    }
    __syncthreads();

    // ---------------- load audio (x stays in registers) ----------------
    const float ing  = sh_gain[0];
    const float outg = sh_gain[1];
    float x[SPT];
    {
        const float4* ap = (const float4*)(audio + (size_t)b * 49152 + f * FRAME + t * SPT);
        #pragma unroll
        for (int j = 0; j < 4; j++) {
            float4 v = ap[j];
            x[4 * j + 0] = v.x * ing;
            x[4 * j + 1] = v.y * ing;
            x[4 * j + 2] = v.z * ing;
            x[4 * j + 3] = v.w * ing;
        }
    }

    const ull* src_base = (f > 0) ? &g_state[((size_t)b * NFR + (f - 1)) * NB] : nullptr;
    ull* dst_base = (f < NFR - 1) ? &g_state[((size_t)b * NFR + f) * NB] : nullptr;

    // ---------------- filter cascade ----------------
    for (int i = 0; i < NB; i++) {
        const int buf = i & 1;
        const float a1 = cf[i][0], a2 = cf[i][1], a3 = cf[i][2];
        const float m0 = cf[i][3], m1 = cf[i][4], m2 = cf[i][5];

        // prefetch predecessor frame state (broadcast; hidden under sim+scan)
        ull v = 0ull;
        if (f > 0) v = ld_relaxed_u64(src_base + i);

        // u_0 = (m1,m2) . W,  W = [[a1,-a2],[a1*a2, 1-a3-a2^2]]
        float u1 = a1 * fmaf(m2, a2, m1);
        float u2 = fmaf(m2, 1.0f - a3 - a2 * a2, -(m1 * a2));

        // zero-state sim in two independent 8-sample halves; outputs y0
        // emitted on the fly (off the recurrence chain)
        float d01, d02;         // half-0 end state
        float c1, c2;           // half-1 end state
        {
            float p1 = 0.0f, p2 = 0.0f, q1 = 0.0f, q2 = 0.0f;
            #pragma unroll
            for (int j = 0; j < 8; j++) {
                // half 0, sample j
                {
                    float xn = x[j];
                    float v3 = xn - p2;
                    float v1 = fmaf(a1, p1, a2 * v3);
                    float v2 = fmaf(a2, v1, fmaf(a3, v3, p2));
                    x[j] = fmaf(m0, xn, fmaf(m1, v1, m2 * v2));
                    p1 = fmaf(2.0f, v1, -p1);
                    p2 = fmaf(2.0f, v2, -p2);
                }
                // half 1, sample j+8 (independent chain)
                {
                    float xn = x[j + 8];
                    float v3 = xn - q2;
                    float v1 = fmaf(a1, q1, a2 * v3);
                    float v2 = fmaf(a2, v1, fmaf(a3, v3, q2));
                    x[j + 8] = fmaf(m0, xn, fmaf(m1, v1, m2 * v2));
                    q1 = fmaf(2.0f, v1, -q1);
                    q2 = fmaf(2.0f, v2, -q2);
                }
            }
            d01 = p1; d02 = p2;
            c1 = q1; c2 = q2;
        }

        // transition matrices: A, A^8, A^16
        M2 A;
        A.a = fmaf(2.0f, a1, -1.0f);
        A.b = -2.0f * a2;
        A.c = 2.0f * a1 * a2;
        A.d = 1.0f - 2.0f * fmaf(a2, a2, a3);
        M2 A8 = msq(msq(msq(A)));
        M2 M  = msq(A8);            // A^16

        // combined 16-sample segment offset = A^8 * d0 + d1
        {
            float n1 = fmaf(A8.a, d01, fmaf(A8.b, d02, c1));
            float n2 = fmaf(A8.c, d01, fmaf(A8.d, d02, c2));
            c1 = n1; c2 = n2;
        }

        // warp affine scan; simultaneously build L = A^(16*lane)
        M2 L; L.a = 1.0f; L.b = 0.0f; L.c = 0.0f; L.d = 1.0f;
        #pragma unroll
        for (int k = 0; k < 5; k++) {
            float o1 = __shfl_up_sync(0xFFFFFFFFu, c1, 1 << k);
            float o2 = __shfl_up_sync(0xFFFFFFFFu, c2, 1 << k);
            if (lane >= (1 << k)) {
                c1 = fmaf(M.a, o1, fmaf(M.b, o2, c1));
                c2 = fmaf(M.c, o1, fmaf(M.d, o2, c2));
            }
            if (lane & (1 << k)) L = mmul(M, L);
            M = msq(M);             // after loop: M = A^512
        }

        // within-warp exclusive offset
        float e1 = __shfl_up_sync(0xFFFFFFFFu, c1, 1);
        float e2 = __shfl_up_sync(0xFFFFFFFFu, c2, 1);
        if (lane == 0) { e1 = 0.0f; e2 = 0.0f; }

        if (lane == 31) { shTa[buf][w] = c1; shTb[buf][w] = c2; }
        __syncthreads();

        // finish the spin if the prefetch raced the predecessor
        if (f > 0 && v == SVAL) {
            do { __nanosleep(32); v = ld_relaxed_u64(src_base + i); } while (v == SVAL);
        }
        const float si1 = __uint_as_float((unsigned)(v & 0xFFFFFFFFu));
        const float si2 = __uint_as_float((unsigned)(v >> 32));

        // thread 0 (warp 0 has no chain work): compute frame-out, publish ASAP
        if (t == 0 && dst_base != nullptr) {
            float S1 = si1, S2 = si2;
            #pragma unroll
            for (int j = 0; j < NW; j++) {
                float n1 = fmaf(M.a, S1, fmaf(M.b, S2, shTa[buf][j]));
                float n2 = fmaf(M.c, S1, fmaf(M.d, S2, shTb[buf][j]));
                S1 = n1; S2 = n2;
            }
            ull pv = ((ull)__float_as_uint(S2) << 32) | (ull)__float_as_uint(S1);
            st_relaxed_u64(dst_base + i, pv);
        }

        // warp-in state: chain through earlier warps' totals (warp-uniform)
        float S1 = si1, S2 = si2;
        #pragma unroll
        for (int j = 0; j < NW - 1; j++) {
            if (j < w) {
                float n1 = fmaf(M.a, S1, fmaf(M.b, S2, shTa[buf][j]));
                float n2 = fmaf(M.c, S1, fmaf(M.d, S2, shTb[buf][j]));
                S1 = n1; S2 = n2;
            }
        }

        // thread-in state = L * S_w + e
        float s1 = fmaf(L.a, S1, fmaf(L.b, S2, e1));
        float s2 = fmaf(L.c, S1, fmaf(L.d, S2, e2));

        // half-1 incoming homogeneous state t1 = A^8 * s + d0
        float t11 = fmaf(A8.a, s1, fmaf(A8.b, s2, d01));
        float t12 = fmaf(A8.c, s1, fmaf(A8.d, s2, d02));

        // superposition correction: x[j] += u_j . state, u advances by A
        #pragma unroll
        for (int j = 0; j < 8; j++) {
            x[j]     = fmaf(u1, s1,  fmaf(u2, s2,  x[j]));
            x[j + 8] = fmaf(u1, t11, fmaf(u2, t12, x[j + 8]));
            float nu1 = fmaf(u1, A.a, u2 * A.c);
            float nu2 = fmaf(u1, A.b, u2 * A.d);
            u1 = nu1; u2 = nu2;
        }
    }

    // ---------------- store output ----------------
    {
        float4* op = (float4*)(out + (size_t)b * 49152 + f * FRAME + t * SPT);
        #pragma unroll
        for (int j = 0; j < 4; j++) {
            float4 v;
            v.x = x[4 * j + 0] * outg;
            v.y = x[4 * j + 1] * outg;
            v.z = x[4 * j + 2] * outg;
            v.w = x[4 * j + 3] * outg;
            op[j] = v;
        }
    }
}

extern "C" void kernel_launch(void* const* d_in, const int* in_sizes, int n_in,
                              void* d_out, int out_size) {
    const float* audio;
    const float* params;
    if (in_sizes[0] > in_sizes[1]) { audio = (const float*)d_in[0]; params = (const float*)d_in[1]; }
    else                           { audio = (const float*)d_in[1]; params = (const float*)d_in[0]; }
    float* out = (float*)d_out;

    init_state_kernel<<<(BATCH * NFR * NB + 255) / 256, 256>>>();
    eq_kernel<<<BATCH * NFR, TPB>>>(audio, params, out);
}

// round 12
// speedup vs baseline: 1.2151x; 1.1063x over previous
#include <cuda_runtime.h>
#include <cstdint>

// ---------------------------------------------------------------------------
// DifferentiableBiquadChain: 16 cascaded SVF biquads, per-frame coefficients.
//
// Block = (batch b, frame f), 128 threads x 16 samples each.
// Setup: thread i precomputes ALL block-uniform per-filter data (affine sim
// form Aa..Ad,b1,b2,h,w; A^8; A^16..A^256 scan matrices; A^512) into smem
// float4 slots — threads no longer recompute matrix powers per filter.
// Per filter: prefetch predecessor state -> zero-state sim in two 8-sample
// halves (affine form, y emitted on the fly) -> half combine (A^8) -> warp
// affine scan (+L build from smem matrices) -> ONE barrier -> per-warp chain
// -> publish (thread 0) -> superposition correction x += u_j . s.
// ---------------------------------------------------------------------------

#define NB      16
#define FRAME   2048
#define NFR     24
#define BATCH   32
#define TPB     128
#define SPT     16
#define NW      4
#define SVAL    0xFFFFFFFFFFFFFFFFull

typedef unsigned long long ull;

__device__ ull g_state[BATCH * NFR * NB];

__global__ void init_state_kernel() {
    int i = blockIdx.x * blockDim.x + threadIdx.x;
    if (i < BATCH * NFR * NB) g_state[i] = SVAL;
}

struct M2 { float a, b, c, d; }; // [[a,b],[c,d]]

__device__ __forceinline__ M2 msq(M2 m) {
    M2 r;
    float apd = m.a + m.d;
    float bc  = m.b * m.c;
    r.a = fmaf(m.a, m.a, bc);
    r.b = m.b * apd;
    r.c = m.c * apd;
    r.d = fmaf(m.d, m.d, bc);
    return r;
}

__device__ __forceinline__ ull ld_relaxed_u64(const ull* p) {
    ull v;
    asm volatile("ld.relaxed.gpu.global.u64 %0, [%1];" : "=l"(v) : "l"(p) : "memory");
    return v;
}
__device__ __forceinline__ void st_relaxed_u64(ull* p, ull v) {
    asm volatile("st.relaxed.gpu.global.u64 [%0], %1;" : : "l"(p), "l"(v) : "memory");
}

// smem slot indices (float4 per filter)
//  0: {Aa, Ab, b1, h}
//  1: {Ac, Ad, b2, 0}
//  2: {w1, w2, 0, 0}
//  3: A^8
//  4: A^512
//  5..9: A^16, A^32, A^64, A^128, A^256

__global__ __launch_bounds__(TPB, 6)
void eq_kernel(const float* __restrict__ audio,
               const float* __restrict__ params,
               float* __restrict__ out)
{
    const int blk  = blockIdx.x;
    const int f    = blk >> 5;   // frame (f-major: predecessors have lower blockIdx)
    const int b    = blk & 31;   // batch
    const int t    = threadIdx.x;
    const int lane = t & 31;
    const int w    = t >> 5;

    __shared__ float4 um[NB][10];     // uniform per-filter data
    __shared__ float  sh_gain[2];     // in_g, out_g
    __shared__ float  shTa[2][NW];    // warp totals c1 (double-buffered)
    __shared__ float  shTb[2][NW];    // warp totals c2

    // ---------------- setup: thread i builds filter i's uniforms ----------------
    if (t < NB) {
        const float* pb = params + (size_t)(b * 50) * NFR + f;
        float fn = pb[(t * 3 + 0) * NFR];
        float gn = pb[(t * 3 + 1) * NFR];
        float qn = pb[(t * 3 + 2) * NFR];

        float Q = expf(fmaf(qn, 3.4657359f, -0.6931472f));
        Q = fminf(fmaxf(Q, 0.1f), 100.0f);

        float gain = fmaf(gn, 48.0f, -24.0f);
        float A  = exp10f(gain * 0.025f);   // 10^(gain/40)
        float sA = sqrtf(A);

        float lnlo, lnhi;
        if      (t == 0)            { lnlo = 2.9957323f; lnhi = 6.2146081f; } // HPF 20..500
        else if (t == 15)           { lnlo = 8.5171932f; lnhi = 9.9034876f; } // LPF 5k..20k
        else if (t == 1 || t == 14) { lnlo = 3.9120230f; lnhi = 9.6803184f; } // shelf 50..16k
        else                        { lnlo = 4.6051702f; lnhi = 9.6158055f; } // peak 100..15k
        float fc = expf(fmaf(fn, (lnhi - lnlo), lnlo));
        float g  = tanf(fc * 3.27249235e-5f);           // tan(pi*fc/96000)
        g = fminf(fmaxf(g, 1e-6f), 100.0f);

        float a1, a2, a3, m0, m1, m2;
        if (t == 0) {            // highpass
            float k = 1.0f / Q;
            a1 = 1.0f / (1.0f + g * (g + k)); a2 = g * a1; a3 = g * a2;
            m0 = 1.0f; m1 = -k; m2 = -1.0f;
        } else if (t == 15) {    // lowpass
            float k = 1.0f / Q;
            a1 = 1.0f / (1.0f + g * (g + k)); a2 = g * a1; a3 = g * a2;
            m0 = 0.0f; m1 = 0.0f; m2 = 1.0f;
        } else if (t == 1) {     // lowshelf
            float k = 1.0f / Q;
            float gs = (gain >= 0.0f) ? (g / sA) : (g * sA);
            a1 = 1.0f / (1.0f + gs * (gs + k)); a2 = gs * a1; a3 = gs * a2;
            m0 = 1.0f; m1 = k * (A - 1.0f); m2 = A * A - 1.0f;
        } else if (t == 14) {    // highshelf
            float k = 1.0f / Q;
            float gs = (gain >= 0.0f) ? (g * sA) : (g / sA);
            a1 = 1.0f / (1.0f + gs * (gs + k)); a2 = gs * a1; a3 = gs * a2;
            m0 = A * A; m1 = k * (1.0f - A) * A; m2 = 1.0f - A * A;
        } else {                 // peak
            float k = (gain >= 0.0f) ? (1.0f / (Q * A)) : (A / Q);
            a1 = 1.0f / (1.0f + g * (g + k)); a2 = g * a1; a3 = g * a2;
            m0 = 1.0f; m1 = k * (A * A - 1.0f); m2 = 0.0f;
        }

        // affine sim form: s' = Am*s + b*x,  y = h*x + w . s
        M2 Am;
        Am.a = fmaf(2.0f, a1, -1.0f);
        Am.b = -2.0f * a2;
        Am.c = 2.0f * a1 * a2;
        Am.d = 1.0f - 2.0f * fmaf(a2, a2, a3);
        float aa  = a2 * a2 + a3;            // a2^2 + a3
        float b1v = 2.0f * a2;
        float b2v = 2.0f * aa;
        float h   = fmaf(m1, a2, fmaf(m2, aa, m0));
        float w1  = a1 * fmaf(m2, a2, m1);
        float w2  = fmaf(m2, 1.0f - a3 - a2 * a2, -(m1 * a2));

        M2 A8  = msq(msq(msq(Am)));
        M2 M0  = msq(A8);        // A^16
        M2 M1  = msq(M0);
        M2 M2m = msq(M1);
        M2 M3  = msq(M2m);
        M2 M4  = msq(M3);
        M2 A512 = msq(M4);

        um[t][0] = make_float4(Am.a, Am.b, b1v, h);
        um[t][1] = make_float4(Am.c, Am.d, b2v, 0.0f);
        um[t][2] = make_float4(w1, w2, 0.0f, 0.0f);
        um[t][3] = make_float4(A8.a, A8.b, A8.c, A8.d);
        um[t][4] = make_float4(A512.a, A512.b, A512.c, A512.d);
        um[t][5] = make_float4(M0.a, M0.b, M0.c, M0.d);
        um[t][6] = make_float4(M1.a, M1.b, M1.c, M1.d);
        um[t][7] = make_float4(M2m.a, M2m.b, M2m.c, M2m.d);
        um[t][8] = make_float4(M3.a, M3.b, M3.c, M3.d);
        um[t][9] = make_float4(M4.a, M4.b, M4.c, M4.d);
    } else if (t == 16 || t == 17) {
        float n  = params[(size_t)(b * 50 + 48 + (t - 16)) * NFR + f];
        float db = fmaf(n, 60.0f, -60.0f);
        sh_gain[t - 16] = exp10f(db * 0.05f);  // 10^(db/20)
    }
    __syncthreads();

    // ---------------- load audio (x stays in registers) ----------------
    const float ing  = sh_gain[0];
    const float outg = sh_gain[1];
    float x[SPT];
    {
        const float4* ap = (const float4*)(audio + (size_t)b * 49152 + f * FRAME + t * SPT);
        #pragma unroll
        for (int j = 0; j < 4; j++) {
            float4 v = ap[j];
            x[4 * j + 0] = v.x * ing;
            x[4 * j + 1] = v.y * ing;
            x[4 * j + 2] = v.z * ing;
            x[4 * j + 3] = v.w * ing;
        }
    }

    const ull* src_base = (f > 0) ? &g_state[((size_t)b * NFR + (f - 1)) * NB] : nullptr;
    ull* dst_base = (f < NFR - 1) ? &g_state[((size_t)b * NFR + f) * NB] : nullptr;

    // ---------------- filter cascade ----------------
    for (int i = 0; i < NB; i++) {
        const int buf = i & 1;

        // prefetch predecessor frame state (broadcast; hidden under sim+scan)
        ull v = 0ull;
        if (f > 0) v = ld_relaxed_u64(src_base + i);

        const float4 U0 = um[i][0];   // Aa Ab b1 h
        const float4 U1 = um[i][1];   // Ac Ad b2 -
        const float4 U2 = um[i][2];   // w1 w2 - -
        const float4 A8 = um[i][3];

        // zero-state sim in two independent 8-sample halves (affine form);
        // y emitted on the fly, off the state chains
        float d01, d02, c1, c2;
        {
            float p1 = 0.0f, p2 = 0.0f, q1 = 0.0f, q2 = 0.0f;
            #pragma unroll
            for (int j = 0; j < 8; j++) {
                {
                    float xn = x[j];
                    float y  = fmaf(U0.w, xn, fmaf(U2.x, p1, U2.y * p2));
                    float n1 = fmaf(U0.x, p1, fmaf(U0.y, p2, U0.z * xn));
                    float n2 = fmaf(U1.x, p1, fmaf(U1.y, p2, U1.z * xn));
                    x[j] = y; p1 = n1; p2 = n2;
                }
                {
                    float xn = x[j + 8];
                    float y  = fmaf(U0.w, xn, fmaf(U2.x, q1, U2.y * q2));
                    float n1 = fmaf(U0.x, q1, fmaf(U0.y, q2, U0.z * xn));
                    float n2 = fmaf(U1.x, q1, fmaf(U1.y, q2, U1.z * xn));
                    x[j + 8] = y; q1 = n1; q2 = n2;
                }
            }
            d01 = p1; d02 = p2;
            // combined 16-sample segment offset = A^8 * d0 + d1
            c1 = fmaf(A8.x, p1, fmaf(A8.y, p2, q1));
            c2 = fmaf(A8.z, p1, fmaf(A8.w, p2, q2));
        }

        // warp affine scan with precomputed level matrices; build L = A^(16*lane)
        float La = 1.0f, Lb = 0.0f, Lc = 0.0f, Ld = 0.0f; // Ld set below
        Ld = 1.0f;
        #pragma unroll
        for (int k = 0; k < 5; k++) {
            const float4 Mk = um[i][5 + k];
            float o1 = __shfl_up_sync(0xFFFFFFFFu, c1, 1 << k);
            float o2 = __shfl_up_sync(0xFFFFFFFFu, c2, 1 << k);
            if (lane >= (1 << k)) {
                c1 = fmaf(Mk.x, o1, fmaf(Mk.y, o2, c1));
                c2 = fmaf(Mk.z, o1, fmaf(Mk.w, o2, c2));
            }
            if (lane & (1 << k)) {
                float na = fmaf(Mk.x, La, Mk.y * Lc);
                float nb = fmaf(Mk.x, Lb, Mk.y * Ld);
                float nc = fmaf(Mk.z, La, Mk.w * Lc);
                float nd = fmaf(Mk.z, Lb, Mk.w * Ld);
                La = na; Lb = nb; Lc = nc; Ld = nd;
            }
        }

        // within-warp exclusive offset
        float e1 = __shfl_up_sync(0xFFFFFFFFu, c1, 1);
        float e2 = __shfl_up_sync(0xFFFFFFFFu, c2, 1);
        if (lane == 0) { e1 = 0.0f; e2 = 0.0f; }

        if (lane == 31) { shTa[buf][w] = c1; shTb[buf][w] = c2; }
        __syncthreads();

        // finish the spin if the prefetch raced the predecessor
        if (f > 0 && v == SVAL) {
            do { __nanosleep(32); v = ld_relaxed_u64(src_base + i); } while (v == SVAL);
        }
        const float si1 = __uint_as_float((unsigned)(v & 0xFFFFFFFFu));
        const float si2 = __uint_as_float((unsigned)(v >> 32));

        const float4 A512 = um[i][4];

        // thread 0 (warp 0 has no chain work): compute frame-out, publish ASAP
        if (t == 0 && dst_base != nullptr) {
            float S1 = si1, S2 = si2;
            #pragma unroll
            for (int j = 0; j < NW; j++) {
                float n1 = fmaf(A512.x, S1, fmaf(A512.y, S2, shTa[buf][j]));
                float n2 = fmaf(A512.z, S1, fmaf(A512.w, S2, shTb[buf][j]));
                S1 = n1; S2 = n2;
            }
            ull pv = ((ull)__float_as_uint(S2) << 32) | (ull)__float_as_uint(S1);
            st_relaxed_u64(dst_base + i, pv);
        }

        // warp-in state: chain through earlier warps' totals (warp-uniform)
        float S1 = si1, S2 = si2;
        #pragma unroll
        for (int j = 0; j < NW - 1; j++) {
            if (j < w) {
                float n1 = fmaf(A512.x, S1, fmaf(A512.y, S2, shTa[buf][j]));
                float n2 = fmaf(A512.z, S1, fmaf(A512.w, S2, shTb[buf][j]));
                S1 = n1; S2 = n2;
            }
        }

        // thread-in state = L * S_w + e
        float s1 = fmaf(La, S1, fmaf(Lb, S2, e1));
        float s2 = fmaf(Lc, S1, fmaf(Ld, S2, e2));

        // half-1 incoming homogeneous state t1 = A^8 * s + d0
        float t11 = fmaf(A8.x, s1, fmaf(A8.y, s2, d01));
        float t12 = fmaf(A8.z, s1, fmaf(A8.w, s2, d02));

        // superposition correction: x[j] += u_j . state, u_0 = w, u <- u * A
        float u1 = U2.x, u2 = U2.y;
        #pragma unroll
        for (int j = 0; j < 8; j++) {
            x[j]     = fmaf(u1, s1,  fmaf(u2, s2,  x[j]));
            x[j + 8] = fmaf(u1, t11, fmaf(u2, t12, x[j + 8]));
            float nu1 = fmaf(u1, U0.x, u2 * U1.x);
            float nu2 = fmaf(u1, U0.y, u2 * U1.y);
            u1 = nu1; u2 = nu2;
        }
    }

    // ---------------- store output ----------------
    {
        float4* op = (float4*)(out + (size_t)b * 49152 + f * FRAME + t * SPT);
        #pragma unroll
        for (int j = 0; j < 4; j++) {
            float4 v;
            v.x = x[4 * j + 0] * outg;
            v.y = x[4 * j + 1] * outg;
            v.z = x[4 * j + 2] * outg;
            v.w = x[4 * j + 3] * outg;
            op[j] = v;
        }
    }
}

extern "C" void kernel_launch(void* const* d_in, const int* in_sizes, int n_in,
                              void* d_out, int out_size) {
    const float* audio;
    const float* params;
    if (in_sizes[0] > in_sizes[1]) { audio = (const float*)d_in[0]; params = (const float*)d_in[1]; }
    else                           { audio = (const float*)d_in[1]; params = (const float*)d_in[0]; }
    float* out = (float*)d_out;

    init_state_kernel<<<(BATCH * NFR * NB + 255) / 256, 256>>>();
    eq_kernel<<<BATCH * NFR, TPB>>>(audio, params, out);
}

// round 13
// speedup vs baseline: 1.2372x; 1.0182x over previous
#include <cuda_runtime.h>
#include <cstdint>

// ---------------------------------------------------------------------------
// DifferentiableBiquadChain: 16 cascaded SVF biquads, per-frame coefficients.
//
// Block = (batch b, frame f), 128 threads x 16 samples each.
// Setup: thread i precomputes ALL block-uniform per-filter data into smem:
// affine sim form (A, b, h, w), A^8, scan matrices A^16..A^256, A^512, and
// the 8 superposition row-vectors u_j = w.A^j. Per filter: prefetch
// predecessor state -> zero-state sim in two 8-sample halves (affine form,
// y emitted on the fly) -> half combine (A^8) -> warp affine scan -> ONE
// barrier -> per-warp chain -> publish (thread 0) -> per-lane propagation
// z = A^(16*lane).S_w via 5 predicated matvecs -> correction x += u_j . s
// with u_j loaded from smem (no per-thread u-advance, no L-matrix build).
// ---------------------------------------------------------------------------

#define NB      16
#define FRAME   2048
#define NFR     24
#define BATCH   32
#define TPB     128
#define SPT     16
#define NW      4
#define SVAL    0xFFFFFFFFFFFFFFFFull

typedef unsigned long long ull;

__device__ ull g_state[BATCH * NFR * NB];

__global__ void init_state_kernel() {
    int i = blockIdx.x * blockDim.x + threadIdx.x;
    if (i < BATCH * NFR * NB) g_state[i] = SVAL;
}

struct M2 { float a, b, c, d; }; // [[a,b],[c,d]]

__device__ __forceinline__ M2 msq(M2 m) {
    M2 r;
    float apd = m.a + m.d;
    float bc  = m.b * m.c;
    r.a = fmaf(m.a, m.a, bc);
    r.b = m.b * apd;
    r.c = m.c * apd;
    r.d = fmaf(m.d, m.d, bc);
    return r;
}

__device__ __forceinline__ ull ld_relaxed_u64(const ull* p) {
    ull v;
    asm volatile("ld.relaxed.gpu.global.u64 %0, [%1];" : "=l"(v) : "l"(p) : "memory");
    return v;
}
__device__ __forceinline__ void st_relaxed_u64(ull* p, ull v) {
    asm volatile("st.relaxed.gpu.global.u64 [%0], %1;" : : "l"(p), "l"(v) : "memory");
}

// smem slot indices (float4 per filter)
//  0: {Aa, Ab, b1, h}
//  1: {Ac, Ad, b2, 0}
//  2: {w1, w2, 0, 0}
//  3: A^8
//  4: A^512
//  5..9:  A^16, A^32, A^64, A^128, A^256
// 10..13: {u1_j, u2_j, u1_{j+1}, u2_{j+1}} for j = 0,2,4,6

__global__ __launch_bounds__(TPB, 6)
void eq_kernel(const float* __restrict__ audio,
               const float* __restrict__ params,
               float* __restrict__ out)
{
    const int blk  = blockIdx.x;
    const int f    = blk >> 5;   // frame (f-major: predecessors have lower blockIdx)
    const int b    = blk & 31;   // batch
    const int t    = threadIdx.x;
    const int lane = t & 31;
    const int w    = t >> 5;

    __shared__ float4 um[NB][14];     // uniform per-filter data
    __shared__ float  sh_gain[2];     // in_g, out_g
    __shared__ float  shTa[2][NW];    // warp totals c1 (double-buffered)
    __shared__ float  shTb[2][NW];    // warp totals c2

    // ---------------- setup: thread i builds filter i's uniforms ----------------
    if (t < NB) {
        const float* pb = params + (size_t)(b * 50) * NFR + f;
        float fn = pb[(t * 3 + 0) * NFR];
        float gn = pb[(t * 3 + 1) * NFR];
        float qn = pb[(t * 3 + 2) * NFR];

        float Q = expf(fmaf(qn, 3.4657359f, -0.6931472f));
        Q = fminf(fmaxf(Q, 0.1f), 100.0f);

        float gain = fmaf(gn, 48.0f, -24.0f);
        float A  = exp10f(gain * 0.025f);   // 10^(gain/40)
        float sA = sqrtf(A);

        float lnlo, lnhi;
        if      (t == 0)            { lnlo = 2.9957323f; lnhi = 6.2146081f; } // HPF 20..500
        else if (t == 15)           { lnlo = 8.5171932f; lnhi = 9.9034876f; } // LPF 5k..20k
        else if (t == 1 || t == 14) { lnlo = 3.9120230f; lnhi = 9.6803184f; } // shelf 50..16k
        else                        { lnlo = 4.6051702f; lnhi = 9.6158055f; } // peak 100..15k
        float fc = expf(fmaf(fn, (lnhi - lnlo), lnlo));
        float g  = tanf(fc * 3.27249235e-5f);           // tan(pi*fc/96000)
        g = fminf(fmaxf(g, 1e-6f), 100.0f);

        float a1, a2, a3, m0, m1, m2;
        if (t == 0) {            // highpass
            float k = 1.0f / Q;
            a1 = 1.0f / (1.0f + g * (g + k)); a2 = g * a1; a3 = g * a2;
            m0 = 1.0f; m1 = -k; m2 = -1.0f;
        } else if (t == 15) {    // lowpass
            float k = 1.0f / Q;
            a1 = 1.0f / (1.0f + g * (g + k)); a2 = g * a1; a3 = g * a2;
            m0 = 0.0f; m1 = 0.0f; m2 = 1.0f;
        } else if (t == 1) {     // lowshelf
            float k = 1.0f / Q;
            float gs = (gain >= 0.0f) ? (g / sA) : (g * sA);
            a1 = 1.0f / (1.0f + gs * (gs + k)); a2 = gs * a1; a3 = gs * a2;
            m0 = 1.0f; m1 = k * (A - 1.0f); m2 = A * A - 1.0f;
        } else if (t == 14) {    // highshelf
            float k = 1.0f / Q;
            float gs = (gain >= 0.0f) ? (g * sA) : (g / sA);
            a1 = 1.0f / (1.0f + gs * (gs + k)); a2 = gs * a1; a3 = gs * a2;
            m0 = A * A; m1 = k * (1.0f - A) * A; m2 = 1.0f - A * A;
        } else {                 // peak
            float k = (gain >= 0.0f) ? (1.0f / (Q * A)) : (A / Q);
            a1 = 1.0f / (1.0f + g * (g + k)); a2 = g * a1; a3 = g * a2;
            m0 = 1.0f; m1 = k * (A * A - 1.0f); m2 = 0.0f;
        }

        // affine sim form: s' = Am*s + bv*x,  y = h*x + w . s
        M2 Am;
        Am.a = fmaf(2.0f, a1, -1.0f);
        Am.b = -2.0f * a2;
        Am.c = 2.0f * a1 * a2;
        Am.d = 1.0f - 2.0f * fmaf(a2, a2, a3);
        float aa  = a2 * a2 + a3;
        float b1v = 2.0f * a2;
        float b2v = 2.0f * aa;
        float h   = fmaf(m1, a2, fmaf(m2, aa, m0));
        float w1  = a1 * fmaf(m2, a2, m1);
        float w2  = fmaf(m2, 1.0f - a3 - a2 * a2, -(m1 * a2));

        M2 A8  = msq(msq(msq(Am)));
        M2 M0  = msq(A8);        // A^16
        M2 M1  = msq(M0);
        M2 M2m = msq(M1);
        M2 M3  = msq(M2m);
        M2 M4  = msq(M3);
        M2 A512 = msq(M4);

        um[t][0] = make_float4(Am.a, Am.b, b1v, h);
        um[t][1] = make_float4(Am.c, Am.d, b2v, 0.0f);
        um[t][2] = make_float4(w1, w2, 0.0f, 0.0f);
        um[t][3] = make_float4(A8.a, A8.b, A8.c, A8.d);
        um[t][4] = make_float4(A512.a, A512.b, A512.c, A512.d);
        um[t][5] = make_float4(M0.a, M0.b, M0.c, M0.d);
        um[t][6] = make_float4(M1.a, M1.b, M1.c, M1.d);
        um[t][7] = make_float4(M2m.a, M2m.b, M2m.c, M2m.d);
        um[t][8] = make_float4(M3.a, M3.b, M3.c, M3.d);
        um[t][9] = make_float4(M4.a, M4.b, M4.c, M4.d);

        // superposition rows u_j = w . A^j, j = 0..7 (pairs per float4)
        float u1 = w1, u2 = w2;
        #pragma unroll
        for (int j = 0; j < 4; j++) {
            float p1 = u1, p2 = u2;
            float q1 = fmaf(u1, Am.a, u2 * Am.c);
            float q2 = fmaf(u1, Am.b, u2 * Am.d);
            um[t][10 + j] = make_float4(p1, p2, q1, q2);
            u1 = fmaf(q1, Am.a, q2 * Am.c);
            u2 = fmaf(q1, Am.b, q2 * Am.d);
        }
    } else if (t == 16 || t == 17) {
        float n  = params[(size_t)(b * 50 + 48 + (t - 16)) * NFR + f];
        float db = fmaf(n, 60.0f, -60.0f);
        sh_gain[t - 16] = exp10f(db * 0.05f);  // 10^(db/20)
    }
    __syncthreads();

    // ---------------- load audio (x stays in registers) ----------------
    const float ing  = sh_gain[0];
    const float outg = sh_gain[1];
    float x[SPT];
    {
        const float4* ap = (const float4*)(audio + (size_t)b * 49152 + f * FRAME + t * SPT);
        #pragma unroll
        for (int j = 0; j < 4; j++) {
            float4 v = ap[j];
            x[4 * j + 0] = v.x * ing;
            x[4 * j + 1] = v.y * ing;
            x[4 * j + 2] = v.z * ing;
            x[4 * j + 3] = v.w * ing;
        }
    }

    const ull* src_base = (f > 0) ? &g_state[((size_t)b * NFR + (f - 1)) * NB] : nullptr;
    ull* dst_base = (f < NFR - 1) ? &g_state[((size_t)b * NFR + f) * NB] : nullptr;

    // ---------------- filter cascade ----------------
    for (int i = 0; i < NB; i++) {
        const int buf = i & 1;

        // prefetch predecessor frame state (broadcast; hidden under sim+scan)
        ull v = 0ull;
        if (f > 0) v = ld_relaxed_u64(src_base + i);

        const float4 U0 = um[i][0];   // Aa Ab b1 h
        const float4 U1 = um[i][1];   // Ac Ad b2 -
        const float4 U2 = um[i][2];   // w1 w2 - -
        const float4 A8 = um[i][3];

        // zero-state sim in two independent 8-sample halves (affine form);
        // y emitted on the fly, off the state chains
        float d01, d02, c1, c2;
        {
            float p1 = 0.0f, p2 = 0.0f, q1 = 0.0f, q2 = 0.0f;
            #pragma unroll
            for (int j = 0; j < 8; j++) {
                {
                    float xn = x[j];
                    float y  = fmaf(U0.w, xn, fmaf(U2.x, p1, U2.y * p2));
                    float n1 = fmaf(U0.x, p1, fmaf(U0.y, p2, U0.z * xn));
                    float n2 = fmaf(U1.x, p1, fmaf(U1.y, p2, U1.z * xn));
                    x[j] = y; p1 = n1; p2 = n2;
                }
                {
                    float xn = x[j + 8];
                    float y  = fmaf(U0.w, xn, fmaf(U2.x, q1, U2.y * q2));
                    float n1 = fmaf(U0.x, q1, fmaf(U0.y, q2, U0.z * xn));
                    float n2 = fmaf(U1.x, q1, fmaf(U1.y, q2, U1.z * xn));
                    x[j + 8] = y; q1 = n1; q2 = n2;
                }
            }
            d01 = p1; d02 = p2;
            // combined 16-sample segment offset = A^8 * d0 + d1
            c1 = fmaf(A8.x, p1, fmaf(A8.y, p2, q1));
            c2 = fmaf(A8.z, p1, fmaf(A8.w, p2, q2));
        }

        // warp affine scan with precomputed level matrices (no L build)
        #pragma unroll
        for (int k = 0; k < 5; k++) {
            const float4 Mk = um[i][5 + k];
            float o1 = __shfl_up_sync(0xFFFFFFFFu, c1, 1 << k);
            float o2 = __shfl_up_sync(0xFFFFFFFFu, c2, 1 << k);
            if (lane >= (1 << k)) {
                c1 = fmaf(Mk.x, o1, fmaf(Mk.y, o2, c1));
                c2 = fmaf(Mk.z, o1, fmaf(Mk.w, o2, c2));
            }
        }

        // within-warp exclusive offset
        float e1 = __shfl_up_sync(0xFFFFFFFFu, c1, 1);
        float e2 = __shfl_up_sync(0xFFFFFFFFu, c2, 1);
        if (lane == 0) { e1 = 0.0f; e2 = 0.0f; }

        if (lane == 31) { shTa[buf][w] = c1; shTb[buf][w] = c2; }
        __syncthreads();

        // finish the spin if the prefetch raced the predecessor
        if (f > 0 && v == SVAL) {
            do { __nanosleep(32); v = ld_relaxed_u64(src_base + i); } while (v == SVAL);
        }
        const float si1 = __uint_as_float((unsigned)(v & 0xFFFFFFFFu));
        const float si2 = __uint_as_float((unsigned)(v >> 32));

        const float4 A512 = um[i][4];

        // thread 0 (warp 0 has no chain work): compute frame-out, publish ASAP
        if (t == 0 && dst_base != nullptr) {
            float S1 = si1, S2 = si2;
            #pragma unroll
            for (int j = 0; j < NW; j++) {
                float n1 = fmaf(A512.x, S1, fmaf(A512.y, S2, shTa[buf][j]));
                float n2 = fmaf(A512.z, S1, fmaf(A512.w, S2, shTb[buf][j]));
                S1 = n1; S2 = n2;
            }
            ull pv = ((ull)__float_as_uint(S2) << 32) | (ull)__float_as_uint(S1);
            st_relaxed_u64(dst_base + i, pv);
        }

        // warp-in state: chain through earlier warps' totals (warp-uniform)
        float S1 = si1, S2 = si2;
        #pragma unroll
        for (int j = 0; j < NW - 1; j++) {
            if (j < w) {
                float n1 = fmaf(A512.x, S1, fmaf(A512.y, S2, shTa[buf][j]));
                float n2 = fmaf(A512.z, S1, fmaf(A512.w, S2, shTb[buf][j]));
                S1 = n1; S2 = n2;
            }
        }

        // per-lane propagation z = A^(16*lane) . S_w (5 predicated matvecs,
        // matrices commute so order is irrelevant)
        #pragma unroll
        for (int k = 0; k < 5; k++) {
            if (lane & (1 << k)) {
                const float4 Mk = um[i][5 + k];
                float n1 = fmaf(Mk.x, S1, Mk.y * S2);
                float n2 = fmaf(Mk.z, S1, Mk.w * S2);
                S1 = n1; S2 = n2;
            }
        }

        // thread-in state = z + e
        float s1 = S1 + e1;
        float s2 = S2 + e2;

        // half-1 incoming homogeneous state t1 = A^8 * s + d0
        float t11 = fmaf(A8.x, s1, fmaf(A8.y, s2, d01));
        float t12 = fmaf(A8.z, s1, fmaf(A8.w, s2, d02));

        // superposition correction with precomputed u_j rows
        #pragma unroll
        for (int j = 0; j < 4; j++) {
            const float4 U = um[i][10 + j];
            x[2 * j]     = fmaf(U.x, s1,  fmaf(U.y, s2,  x[2 * j]));
            x[2 * j + 8] = fmaf(U.x, t11, fmaf(U.y, t12, x[2 * j + 8]));
            x[2 * j + 1] = fmaf(U.z, s1,  fmaf(U.w, s2,  x[2 * j + 1]));
            x[2 * j + 9] = fmaf(U.z, t11, fmaf(U.w, t12, x[2 * j + 9]));
        }
    }

    // ---------------- store output ----------------
    {
        float4* op = (float4*)(out + (size_t)b * 49152 + f * FRAME + t * SPT);
        #pragma unroll
        for (int j = 0; j < 4; j++) {
            float4 v;
            v.x = x[4 * j + 0] * outg;
            v.y = x[4 * j + 1] * outg;
            v.z = x[4 * j + 2] * outg;
            v.w = x[4 * j + 3] * outg;
            op[j] = v;
        }
    }
}

extern "C" void kernel_launch(void* const* d_in, const int* in_sizes, int n_in,
                              void* d_out, int out_size) {
    const float* audio;
    const float* params;
    if (in_sizes[0] > in_sizes[1]) { audio = (const float*)d_in[0]; params = (const float*)d_in[1]; }
    else                           { audio = (const float*)d_in[1]; params = (const float*)d_in[0]; }
    float* out = (float*)d_out;

    init_state_kernel<<<(BATCH * NFR * NB + 255) / 256, 256>>>();
    eq_kernel<<<BATCH * NFR, TPB>>>(audio, params, out);
}